// round 13
// baseline (speedup 1.0000x reference)
#include <cuda_runtime.h>
#include <cstdint>

// FConvLayer: irfft(rfft(x)*rfft(w_pad)) ortho == circular depthwise conv / 64.
// y[b,t,h] = (1/64) * sum_{k<16} w[k,h] * x[b,(t-k) mod 4096,h]
// out = LayerNorm_H(y + x) * ln_w + ln_b
//
// R12: CHANNEL-SPLIT TEAMS. Two warps share one 64-row strip; warp half p
// owns channels [64p, 64p+64), 2 channels per lane (one u64/f32x2).
//  - per-thread state halves (w[16]+acc[16] u64 = 64 regs) -> ~95 regs
//    -> __launch_bounds__(128,5): 20 warps/SM vs 12 before.
//  - scatter conv, cp.async 8B/lane SMEM FIFO (DEPTH=16 slots x 256B/warp).
//  - LN: 5-stage packed butterfly per half, lane0 posts (sum,sumsq) u64 to a
//    4-slot SMEM exchange ring, bar.sync(team,64)/row, FINISH deferred 2 rows
//    reads both halves via one LDS.128.

typedef unsigned long long u64;
#define DINL __device__ __forceinline__

DINL u64 pack2(float lo, float hi) {
    u64 r; asm("mov.b64 %0, {%1,%2};" : "=l"(r) : "f"(lo), "f"(hi)); return r;
}
DINL void unpack2(u64 v, float& lo, float& hi) {
    asm("mov.b64 {%0,%1}, %2;" : "=f"(lo), "=f"(hi) : "l"(v));
}
DINL u64 fma2(u64 a, u64 b, u64 c) {
    u64 d; asm("fma.rn.f32x2 %0,%1,%2,%3;" : "=l"(d) : "l"(a), "l"(b), "l"(c)); return d;
}
DINL u64 add2(u64 a, u64 b) {
    u64 d; asm("add.rn.f32x2 %0,%1,%2;" : "=l"(d) : "l"(a), "l"(b)); return d;
}
DINL u64 sub2(u64 a, u64 b) {
    u64 d; asm("sub.rn.f32x2 %0,%1,%2;" : "=l"(d) : "l"(a), "l"(b)); return d;
}
DINL u64 mul2(u64 a, u64 b) {
    u64 d; asm("mul.rn.f32x2 %0,%1,%2;" : "=l"(d) : "l"(a), "l"(b)); return d;
}
DINL void stcs1(void* p, u64 a) {
    asm volatile("st.global.cs.b64 [%0], %1;" :: "l"(p), "l"(a) : "memory");
}

#define CP8(smem_u32, gptr) \
    asm volatile("cp.async.ca.shared.global [%0], [%1], 8;" \
                 :: "r"(smem_u32), "l"(gptr) : "memory")
#define CP_COMMIT() asm volatile("cp.async.commit_group;" ::: "memory")
#define CP_WAIT(n)  asm volatile("cp.async.wait_group %0;" :: "n"(n) : "memory")
#define TEAM_BAR(id) \
    asm volatile("bar.sync %0, 64;" :: "r"(id) : "memory")

constexpr int S_LEN  = 4096;
constexpr int H_DIM  = 128;
constexpr int K_SZ   = 16;
constexpr int LROWS  = 64;             // rows per team strip
constexpr int DEPTH  = 16;             // FIFO slots per warp
constexpr int ROW_B  = H_DIM * 4;      // 512 B global row stride
constexpr int HALF_B = ROW_B / 2;      // 256 B per warp-half row
constexpr int ROW_U  = H_DIM / 2;      // 64 u64 per global row

// Finish row buffered in parity PP whose exchange slot is SL:
// read both halves' (sum,sumsq), add, normalize my half, stream-store 8B/lane.
#define FINISH_SLOT(PP, SL)                                                   \
    do {                                                                      \
        ulonglong2 both = *reinterpret_cast<const ulonglong2*>(               \
            &xch[team][(SL)][0]);                                             \
        u64 tot = add2(both.x, both.y);                                       \
        float s_, sq_;                                                        \
        unpack2(tot, s_, sq_);                                                \
        const float mean = s_ * (1.0f / 128.0f);                              \
        float var = fmaf(sq_, 1.0f / 128.0f, -mean * mean);                   \
        var = fmaxf(var, 0.0f);                                               \
        const float inv = rsqrtf(var + 1e-12f);                               \
        const u64 inv2  = pack2(inv, inv);                                    \
        const u64 mean2 = pack2(mean, mean);                                  \
        u64 o = fma2(mul2(sub2(hb[(PP)], mean2), inv2), lwv, lbv);            \
        stcs1(wr_g, o);                                                       \
        wr_g += ROW_U;                                                        \
    } while (0)

// One row (slot JJ compile-time). FIN: finish row from two iterations ago
// (parity JJ&1, exchange slot (JJ+2)&3).
#define ROW_BODY(JJ, FIN)                                                     \
    do {                                                                      \
        CP_WAIT(DEPTH - 1);                                                   \
        u64 cur = *reinterpret_cast<const u64*>(ring_c + (JJ) * HALF_B);      \
        if (jo + (JJ) + DEPTH < LROWS) {                                      \
            CP8(ring_s + (JJ) * HALF_B, rd_g);                                \
        }                                                                     \
        CP_COMMIT();                                                          \
        rd_g += ROW_B;                                                        \
        u64 h = add2(fma2(w[0], cur, acc[(JJ)]), cur);                        \
        acc[((JJ) + 15) & (K_SZ - 1)] = mul2(w[15], cur);                     \
        _Pragma("unroll")                                                     \
        for (int k = 1; k < K_SZ - 1; k++) {                                  \
            const int s_ = ((JJ) + k) & (K_SZ - 1);                           \
            acc[s_] = fma2(w[k], cur, acc[s_]);                               \
        }                                                                     \
        float f0, f1;                                                         \
        unpack2(h, f0, f1);                                                   \
        u64 ps = pack2(f0 + f1, fmaf(f0, f0, f1 * f1));                       \
        _Pragma("unroll")                                                     \
        for (int off = 16; off > 0; off >>= 1)                                \
            ps = add2(ps, __shfl_xor_sync(0xffffffffu, ps, off));             \
        if (lane == 0) xch[team][(JJ) & 3][half] = ps;                        \
        TEAM_BAR(team + 1);                                                   \
        if (FIN) { FINISH_SLOT((JJ) & 1, ((JJ) + 2) & 3); }                   \
        hb[(JJ) & 1] = h;                                                     \
    } while (0)

__global__ void __launch_bounds__(128, 5) fconv_ln_kernel(
    const float* __restrict__ x,
    const float* __restrict__ cw,
    const float* __restrict__ lnw,
    const float* __restrict__ lnb,
    float* __restrict__ out)
{
    // FIFO: 4 warps x 16 slots x 256B = 16KB; exchange: 2 teams x 4 x 2 u64.
    __shared__ __align__(16) unsigned char ring[4 * DEPTH * HALF_B];
    __shared__ __align__(16) u64 xch[2][4][2];

    const int lane  = threadIdx.x & 31;
    const int warp  = threadIdx.x >> 5;
    const int team  = warp >> 1;              // 0..1 within CTA
    const int half  = warp & 1;               // channel half
    const int gteam = blockIdx.x * 2 + team;  // global team
    const int spb   = S_LEN / LROWS;          // 64 strips per batch
    const int b     = gteam / spb;
    const int t0    = (gteam % spb) * LROWS;  // multiple of 64

    const char* __restrict__ xb =
        reinterpret_cast<const char*>(x) + (size_t)b * S_LEN * ROW_B;
    // this warp's global column offset within a row: half*256 + lane*8 bytes
    const int coff = half * HALF_B + lane * 8;

    u64* wr_g = reinterpret_cast<u64*>(out)
        + (size_t)b * S_LEN * ROW_U + (size_t)t0 * ROW_U
        + half * (ROW_U / 2) + lane;

    unsigned char* const ring_c = ring + warp * (DEPTH * HALF_B) + lane * 8;
    const uint32_t ring_s = (uint32_t)__cvta_generic_to_shared(ring_c);

    // ---- kick off FIFO: rows t0..t0+15 ----
#pragma unroll
    for (int q = 0; q < DEPTH; q++) {
        CP8(ring_s + q * HALF_B, xb + (size_t)(t0 + q) * ROW_B + coff);
        CP_COMMIT();
    }
    const char* rd_g = xb + (size_t)(t0 + DEPTH) * ROW_B + coff;

    // ---- weights (this warp's 2 channels/lane), pre-scaled by 1/64 ----
    u64 w[K_SZ];
    {
        const char* cwb = reinterpret_cast<const char*>(cw);
        const u64 sc2 = pack2(0.015625f, 0.015625f);
#pragma unroll
        for (int k = 0; k < K_SZ; k++) {
            u64 v = *reinterpret_cast<const u64*>(cwb + k * ROW_B + coff);
            w[k] = mul2(v, sc2);
        }
    }

    // ---- LN params for this lane's 2 channels ----
    u64 lwv = *reinterpret_cast<const u64*>(
        reinterpret_cast<const char*>(lnw) + coff);
    u64 lbv = *reinterpret_cast<const u64*>(
        reinterpret_cast<const char*>(lnb) + coff);

    // ---- forward partial accumulators ----
    u64 acc[K_SZ];
#pragma unroll
    for (int i = 0; i < K_SZ; i++) acc[i] = 0ull;

    // ---- halo: rows t0-15..t0-1 (one-time LDG) ----
#pragma unroll
    for (int i = 0; i < K_SZ - 1; i++) {
        const int r = (t0 - (K_SZ - 1) + i + S_LEN) & (S_LEN - 1);
        u64 v = *reinterpret_cast<const u64*>(xb + (size_t)r * ROW_B + coff);
#pragma unroll
        for (int k = K_SZ - 1 - i; k < K_SZ; k++) {
            const int s = (i + 1 + k) & (K_SZ - 1);
            acc[s] = fma2(w[k], v, acc[s]);
        }
    }

    // ---- 2-row deferred pipeline state ----
    u64 hb[2] = {0ull, 0ull};

    // ---- first block (rows 0..15): rows 0,1 have nothing to finish ----
    {
        const int jo = 0;
#pragma unroll
        for (int j = 0; j < K_SZ; j++) {
            if (j < 2) { ROW_BODY(j, false); }
            else       { ROW_BODY(j, true);  }
        }
    }
#pragma unroll 1
    for (int jo = K_SZ; jo < LROWS; jo += K_SZ) {
#pragma unroll
        for (int j = 0; j < K_SZ; j++) {
            ROW_BODY(j, true);
        }
    }

    // ---- epilogue: rows 62 (parity 0, slot 2) and 63 (parity 1, slot 3) ----
    FINISH_SLOT(0, 2);
    FINISH_SLOT(1, 3);
}

extern "C" void kernel_launch(void* const* d_in, const int* in_sizes, int n_in,
                              void* d_out, int out_size)
{
    const float* x   = (const float*)d_in[0];  // [64, 4096, 128]
    const float* cw  = (const float*)d_in[1];  // [1, 16, 128]
    const float* lnw = (const float*)d_in[2];  // [128]
    const float* lnb = (const float*)d_in[3];  // [128]
    float* out = (float*)d_out;                // [64, 4096, 128]

    // 64 batches x 64 strips = 4096 teams; 2 teams per 128-thread CTA.
    const int blocks = 64 * (S_LEN / LROWS) / 2;    // 2048
    fconv_ln_kernel<<<blocks, 128>>>(x, cw, lnw, lnb, out);
}

// round 17
// speedup vs baseline: 1.6254x; 1.6254x over previous
#include <cuda_runtime.h>
#include <cstdint>

// FConvLayer: irfft(rfft(x)*rfft(w_pad)) ortho == circular depthwise conv / 64.
// y[b,t,h] = (1/64) * sum_{k<16} w[k,h] * x[b,(t-k) mod 4096,h]
// out = LayerNorm_H(y + x) * ln_w + ln_b
//
// R13 = R10 skeleton (best lineage) + PAIRED row processing:
//  - each iteration consumes rows (t, t+1): one CP_WAIT/COMMIT per pair,
//    two independent conv + butterfly chains in flight -> 2x ILP where
//    single-chain latency was exposed.
//  - residual folded into tap 0 (w0 <- 1 + w0/64; halo never uses k=0).
//  - 1 warp = 64-row strip; lane l owns h in [4l,4l+4) (two f32x2 pairs).
//  - 16 forward partial accumulators (scatter); cp.async 16B/lane SMEM FIFO.
//  - LN finish deferred one pair (butterflies overlap next pair's conv).

typedef unsigned long long u64;
#define DINL __device__ __forceinline__

DINL u64 pack2(float lo, float hi) {
    u64 r; asm("mov.b64 %0, {%1,%2};" : "=l"(r) : "f"(lo), "f"(hi)); return r;
}
DINL void unpack2(u64 v, float& lo, float& hi) {
    asm("mov.b64 {%0,%1}, %2;" : "=f"(lo), "=f"(hi) : "l"(v));
}
DINL u64 fma2(u64 a, u64 b, u64 c) {
    u64 d; asm("fma.rn.f32x2 %0,%1,%2,%3;" : "=l"(d) : "l"(a), "l"(b), "l"(c)); return d;
}
DINL u64 add2(u64 a, u64 b) {
    u64 d; asm("add.rn.f32x2 %0,%1,%2;" : "=l"(d) : "l"(a), "l"(b)); return d;
}
DINL u64 sub2(u64 a, u64 b) {
    u64 d; asm("sub.rn.f32x2 %0,%1,%2;" : "=l"(d) : "l"(a), "l"(b)); return d;
}
DINL u64 mul2(u64 a, u64 b) {
    u64 d; asm("mul.rn.f32x2 %0,%1,%2;" : "=l"(d) : "l"(a), "l"(b)); return d;
}
DINL void stcs2(void* p, u64 a, u64 b) {
    asm volatile("st.global.cs.v2.b64 [%0], {%1,%2};"
                 :: "l"(p), "l"(a), "l"(b) : "memory");
}

#define CP16(smem_u32, gptr) \
    asm volatile("cp.async.cg.shared.global [%0], [%1], 16;" \
                 :: "r"(smem_u32), "l"(gptr) : "memory")
#define CP_COMMIT() asm volatile("cp.async.commit_group;" ::: "memory")
#define CP_WAIT(n)  asm volatile("cp.async.wait_group %0;" :: "n"(n) : "memory")

constexpr int S_LEN = 4096;
constexpr int H_DIM = 128;
constexpr int K_SZ  = 16;
constexpr int LROWS = 64;             // rows per warp strip
constexpr int DEPTH = 16;             // SMEM ring slots per warp (8 pair-groups)
constexpr int ROW_B = H_DIM * 4;      // 512 bytes per row
constexpr int ROW_V = H_DIM / 4;      // 32 ulonglong2 per row

// Finish row buffered in parity slot PP: full 5-stage butterfly on packed
// (sum,sumsq), normalize, streaming store at wr_g (rows strictly in order).
#define FINISH_SLOT(PP)                                                       \
    do {                                                                      \
        u64 tot = psb[(PP)];                                                  \
        _Pragma("unroll")                                                     \
        for (int off = 16; off > 0; off >>= 1)                                \
            tot = add2(tot, __shfl_xor_sync(0xffffffffu, tot, off));          \
        float s_, sq_;                                                        \
        unpack2(tot, s_, sq_);                                                \
        const float mean = s_ * (1.0f / 128.0f);                              \
        float var = fmaf(sq_, 1.0f / 128.0f, -mean * mean);                   \
        var = fmaxf(var, 0.0f);                                               \
        const float inv = rsqrtf(var + 1e-12f);                               \
        const u64 inv2  = pack2(inv, inv);                                    \
        const u64 mean2 = pack2(mean, mean);                                  \
        u64 o0 = fma2(mul2(sub2(hb0[(PP)], mean2), inv2), lw[0], lb[0]);      \
        u64 o1 = fma2(mul2(sub2(hb1[(PP)], mean2), inv2), lw[1], lb[1]);      \
        stcs2(wr_g, o0, o1);                                                  \
        wr_g += ROW_V;                                                        \
    } while (0)

// Process rows (jo+JJ, jo+JJ+1); JJ even, compile-time. FIN: finish the
// previous pair (parities 0 then 1) while this pair's conv runs.
#define PAIR_BODY(JJ, FIN)                                                    \
    do {                                                                      \
        CP_WAIT(7);                                                           \
        ulonglong2 cur0 =                                                     \
            *reinterpret_cast<const ulonglong2*>(ring_c + (JJ) * ROW_B);      \
        ulonglong2 cur1 =                                                     \
            *reinterpret_cast<const ulonglong2*>(ring_c + ((JJ)+1) * ROW_B);  \
        if (jo + (JJ) + DEPTH < LROWS) {                                      \
            CP16(ring_s + (JJ) * ROW_B, rd_g);                                \
            CP16(ring_s + ((JJ)+1) * ROW_B, rd_g + ROW_B);                    \
        }                                                                     \
        CP_COMMIT();                                                          \
        rd_g += 2 * ROW_B;                                                    \
        /* consume row JJ (tap0 includes residual: w[0] = 1 + w0/64) */       \
        u64 hx0 = fma2(w[0][0], cur0.x, acc[(JJ)][0]);                        \
        u64 hx1 = fma2(w[0][1], cur0.y, acc[(JJ)][1]);                        \
        /* row JJ's k=1 into slot JJ+1 BEFORE row JJ+1 consumes it */         \
        {                                                                     \
            const int s1 = ((JJ) + 1) & (K_SZ - 1);                           \
            acc[s1][0] = fma2(w[1][0], cur0.x, acc[s1][0]);                   \
            acc[s1][1] = fma2(w[1][1], cur0.y, acc[s1][1]);                   \
        }                                                                     \
        /* consume row JJ+1 */                                                \
        u64 hy0 = fma2(w[0][0], cur1.x, acc[((JJ)+1) & (K_SZ-1)][0]);         \
        u64 hy1 = fma2(w[0][1], cur1.y, acc[((JJ)+1) & (K_SZ-1)][1]);         \
        /* row JJ: k=2..14, then k=15 overwrites slot JJ+15 */                \
        _Pragma("unroll")                                                     \
        for (int k = 2; k < K_SZ - 1; k++) {                                  \
            const int s_ = ((JJ) + k) & (K_SZ - 1);                           \
            acc[s_][0] = fma2(w[k][0], cur0.x, acc[s_][0]);                   \
            acc[s_][1] = fma2(w[k][1], cur0.y, acc[s_][1]);                   \
        }                                                                     \
        {                                                                     \
            const int s15 = ((JJ) + 15) & (K_SZ - 1);                         \
            acc[s15][0] = mul2(w[15][0], cur0.x);                             \
            acc[s15][1] = mul2(w[15][1], cur0.y);                             \
        }                                                                     \
        /* row JJ+1: k=1..14 (slot JJ+15 AFTER overwrite), k=15 -> slot JJ */ \
        _Pragma("unroll")                                                     \
        for (int k = 1; k < K_SZ - 1; k++) {                                  \
            const int s_ = ((JJ) + 1 + k) & (K_SZ - 1);                       \
            acc[s_][0] = fma2(w[k][0], cur1.x, acc[s_][0]);                   \
            acc[s_][1] = fma2(w[k][1], cur1.y, acc[s_][1]);                   \
        }                                                                     \
        acc[(JJ)][0] = mul2(w[15][0], cur1.x);                                \
        acc[(JJ)][1] = mul2(w[15][1], cur1.y);                                \
        /* packed (sum, sumsq) partials for both rows */                      \
        float a0, a1, a2, a3, b0, b1, b2, b3;                                 \
        unpack2(hx0, a0, a1); unpack2(hx1, a2, a3);                           \
        unpack2(hy0, b0, b1); unpack2(hy1, b2, b3);                           \
        u64 psA = pack2((a0 + a1) + (a2 + a3),                                \
                        fmaf(a0, a0, fmaf(a1, a1, fmaf(a2, a2, a3 * a3))));   \
        u64 psB = pack2((b0 + b1) + (b2 + b3),                                \
                        fmaf(b0, b0, fmaf(b1, b1, fmaf(b2, b2, b3 * b3))));   \
        if (FIN) { FINISH_SLOT(0); FINISH_SLOT(1); }                          \
        psb[0] = psA; psb[1] = psB;                                           \
        hb0[0] = hx0; hb1[0] = hx1;                                           \
        hb0[1] = hy0; hb1[1] = hy1;                                           \
    } while (0)

__global__ void __launch_bounds__(128, 3) fconv_ln_kernel(
    const float* __restrict__ x,
    const float* __restrict__ cw,
    const float* __restrict__ lnw,
    const float* __restrict__ lnb,
    float* __restrict__ out)
{
    __shared__ __align__(16) unsigned char ring[4 * DEPTH * ROW_B];  // 32KB

    const int lane  = threadIdx.x & 31;
    const int warp  = threadIdx.x >> 5;
    const int gwarp = (blockIdx.x * blockDim.x + threadIdx.x) >> 5;
    const int spb   = S_LEN / LROWS;          // 64 strips per batch
    const int b     = gwarp / spb;
    const int t0    = (gwarp % spb) * LROWS;  // multiple of 64

    const char* __restrict__ xb =
        reinterpret_cast<const char*>(x) + (size_t)b * S_LEN * ROW_B;
    ulonglong2* wr_g =
        reinterpret_cast<ulonglong2*>(out) + (size_t)b * S_LEN * ROW_V
        + (size_t)t0 * ROW_V + lane;

    unsigned char* const ring_c = ring + warp * (DEPTH * ROW_B) + lane * 16;
    const uint32_t ring_s = (uint32_t)__cvta_generic_to_shared(ring_c);

    // ---- kick off the FIFO: rows t0..t0+15 as 8 pair-groups ----
#pragma unroll
    for (int q = 0; q < DEPTH / 2; q++) {
        CP16(ring_s + (2 * q) * ROW_B,
             xb + (size_t)(t0 + 2 * q) * ROW_B + lane * 16);
        CP16(ring_s + (2 * q + 1) * ROW_B,
             xb + (size_t)(t0 + 2 * q + 1) * ROW_B + lane * 16);
        CP_COMMIT();
    }
    const char* rd_g = xb + (size_t)(t0 + DEPTH) * ROW_B + lane * 16;

    // ---- weights, pre-scaled by 1/64; tap 0 gets +1 (residual fold) ----
    u64 w[K_SZ][2];
    {
        const ulonglong2* cw2 = reinterpret_cast<const ulonglong2*>(cw);
        const u64 sc2 = pack2(0.015625f, 0.015625f);
#pragma unroll
        for (int k = 0; k < K_SZ; k++) {
            ulonglong2 v = cw2[k * ROW_V + lane];
            w[k][0] = mul2(v.x, sc2);
            w[k][1] = mul2(v.y, sc2);
        }
        const u64 one2 = pack2(1.0f, 1.0f);
        w[0][0] = add2(w[0][0], one2);   // halo rows never use tap 0
        w[0][1] = add2(w[0][1], one2);
    }

    // ---- LN params ----
    u64 lw[2], lb[2];
    {
        ulonglong2 v = reinterpret_cast<const ulonglong2*>(lnw)[lane];
        lw[0] = v.x; lw[1] = v.y;
        ulonglong2 u = reinterpret_cast<const ulonglong2*>(lnb)[lane];
        lb[0] = u.x; lb[1] = u.y;
    }

    // ---- forward partial accumulators ----
    u64 acc[K_SZ][2];
#pragma unroll
    for (int i = 0; i < K_SZ; i++) { acc[i][0] = 0ull; acc[i][1] = 0ull; }

    // ---- halo: rows t0-15..t0-1 (one-time LDG); taps k>=1 only ----
    const ulonglong2* xb2 = reinterpret_cast<const ulonglong2*>(xb);
#pragma unroll
    for (int i = 0; i < K_SZ - 1; i++) {
        const int r = (t0 - (K_SZ - 1) + i + S_LEN) & (S_LEN - 1);
        ulonglong2 v = xb2[r * ROW_V + lane];
#pragma unroll
        for (int k = K_SZ - 1 - i; k < K_SZ; k++) {
            const int s = (i + 1 + k) & (K_SZ - 1);
            acc[s][0] = fma2(w[k][0], v.x, acc[s][0]);
            acc[s][1] = fma2(w[k][1], v.y, acc[s][1]);
        }
    }

    // ---- pair-deferred pipeline state ----
    u64 psb[2] = {0ull, 0ull};
    u64 hb0[2] = {0ull, 0ull};
    u64 hb1[2] = {0ull, 0ull};

    // ---- first block (rows 0..15): first pair has nothing to finish ----
    {
        const int jo = 0;
#pragma unroll
        for (int j = 0; j < K_SZ; j += 2) {
            if (j == 0) { PAIR_BODY(j, false); }
            else        { PAIR_BODY(j, true);  }
        }
    }
#pragma unroll 1
    for (int jo = K_SZ; jo < LROWS; jo += K_SZ) {
#pragma unroll
        for (int j = 0; j < K_SZ; j += 2) {
            PAIR_BODY(j, true);
        }
    }

    // ---- epilogue: finish the final pair ----
    FINISH_SLOT(0);
    FINISH_SLOT(1);
}

extern "C" void kernel_launch(void* const* d_in, const int* in_sizes, int n_in,
                              void* d_out, int out_size)
{
    const float* x   = (const float*)d_in[0];  // [64, 4096, 128]
    const float* cw  = (const float*)d_in[1];  // [1, 16, 128]
    const float* lnw = (const float*)d_in[2];  // [128]
    const float* lnb = (const float*)d_in[3];  // [128]
    float* out = (float*)d_out;                // [64, 4096, 128]

    const int total_warps = 64 * (S_LEN / LROWS);   // 4096
    const int blocks = total_warps / 4;             // 1024
    fconv_ln_kernel<<<blocks, 128>>>(x, cw, lnw, lnb, out);
}